// round 11
// baseline (speedup 1.0000x reference)
#include <cuda_runtime.h>
#include <cuda_bf16.h>
#include <cuda_pipeline.h>

// Problem constants (constexpr, not macros)
constexpr int CB  = 2;     // batch
constexpr int CL  = 128;   // seq len
constexpr int CD  = 256;   // model dim
constexpr int CH  = 8;     // heads
constexpr int CDK = 32;    // head dim
constexpr float C_EPS = 1e-6f;
constexpr float C_INV_TEMP = 0.17677669529663687f;   // 1/sqrt(32)

// Scratch (allocation-free rule: __device__ globals)
__device__ float g_pq[CB * CL * CD];
__device__ float g_pk[CB * CL * CD];
__device__ float g_pv[CB * CL * CD];
__device__ float g_dotqk[CB * CH * CL];
__device__ float g_outhead[CB * CL * CD];

// ===========================================================================
// One-shot GEMM tile kernels.
// Tile: 16 rows x 32 cols, K=256 fully resident in smem.
//   As4[64][16] float4:  As4[kk4][r] = A[m0+r][4*kk4 .. 4*kk4+3]   (16 KB)
//   Bs [256][32] float:  Bs[k][c]    = W[k][n0+c]                  (32 KB)
// 256 threads: lr = tid>>4 (row 0..15), lc2 = (tid&15)*2 (col pair).
// All cp.async issued up front; ONE wait; ONE barrier; straight-line FFMA.
// ===========================================================================

// ---------------------------------------------------------------------------
// K1: triple GEMM with fused LayerNorm on the q operand.
//   z=0: pq = LN(q) @ Wq   z=1: pk = k @ Wk   z=2: pv = v @ Wv
// grid=(8,16,3), block=256.
// ---------------------------------------------------------------------------
__global__ __launch_bounds__(256)
void ct_gemm3_kernel(const float* __restrict__ qin,
                     const float* __restrict__ kin,
                     const float* __restrict__ vin,
                     const float* __restrict__ Wq,
                     const float* __restrict__ Wk,
                     const float* __restrict__ Wv,
                     const float* __restrict__ ln_g,
                     const float* __restrict__ ln_b) {
    const int bz = blockIdx.z;
    const float* A; const float* W; float* C;
    if (bz == 0)      { A = qin; W = Wq; C = g_pq; }
    else if (bz == 1) { A = kin; W = Wk; C = g_pk; }
    else              { A = vin; W = Wv; C = g_pv; }

    __shared__ float4 As4[64 * 16];     // 16 KB
    __shared__ float  Bs[256 * 32];     // 32 KB   (total 48 KB exactly)

    int tid = threadIdx.x;
    int m0 = blockIdx.y * 16, n0 = blockIdx.x * 32;

    // ---- issue ALL async copies up front -------------------------------
    // A: 1024 chunks of 16B.  chunk = kk4*16 + r  -> 4 per thread.
    {
        int r   = tid & 15;
        int kk4 = tid >> 4;              // 0..15
#pragma unroll
        for (int it = 0; it < 4; it++) {
            int kk = kk4 + it * 16;      // 0..63
            __pipeline_memcpy_async(&As4[kk * 16 + r],
                                    &A[(m0 + r) * CD + kk * 4], 16);
        }
    }
    // B: 2048 chunks of 16B.  chunk = k*8 + c4 -> 8 per thread.
    {
        int c4 = tid & 7;                // 16B col chunk
        int k0 = tid >> 3;               // 0..31
#pragma unroll
        for (int it = 0; it < 8; it++) {
            int k = k0 + it * 32;        // 0..255
            __pipeline_memcpy_async(&Bs[k * 32 + c4 * 4],
                                    &W[k * CD + n0 + c4 * 4], 16);
        }
    }
    __pipeline_commit();

    // ---- LN stats from GLOBAL while copies are in flight (z==0 only) ---
    float mu_a = 0.f, rs_a = 0.f, mu_b = 0.f, rs_b = 0.f;
    int w = tid >> 5, lane = tid & 31;
    if (bz == 0) {
#pragma unroll
        for (int half = 0; half < 2; half++) {
            int rr = w + half * 8;       // warp w handles rows w and w+8
            const float* rowp = qin + (m0 + rr) * CD;
            float s1 = 0.f, s2 = 0.f;
#pragma unroll
            for (int e = 0; e < 8; e++) {
                float x = rowp[lane + 32 * e];
                s1 += x; s2 += x * x;
            }
#pragma unroll
            for (int o = 16; o > 0; o >>= 1) {
                s1 += __shfl_xor_sync(0xFFFFFFFFu, s1, o);
                s2 += __shfl_xor_sync(0xFFFFFFFFu, s2, o);
            }
            float mu  = s1 * (1.0f / 256.0f);
            float var = s2 * (1.0f / 256.0f) - mu * mu;
            float rs  = rsqrtf(var + C_EPS);
            if (half == 0) { mu_a = mu; rs_a = rs; }
            else           { mu_b = mu; rs_b = rs; }
        }
    }

    __pipeline_wait_prior(0);
    __syncthreads();

    // ---- in-smem LN transform (z==0): warp w owns rows w, w+8 ----------
    if (bz == 0) {
#pragma unroll
        for (int half = 0; half < 2; half++) {
            int rr = w + half * 8;
            float mu = half ? mu_b : mu_a;
            float rs = half ? rs_b : rs_a;
#pragma unroll
            for (int c = 0; c < 2; c++) {
                int kk = lane + c * 32;          // 0..63
                float4 p  = As4[kk * 16 + rr];
                float4 g4 = ((const float4*)ln_g)[kk];
                float4 b4 = ((const float4*)ln_b)[kk];
                p.x = (p.x - mu) * rs * g4.x + b4.x;
                p.y = (p.y - mu) * rs * g4.y + b4.y;
                p.z = (p.z - mu) * rs * g4.z + b4.z;
                p.w = (p.w - mu) * rs * g4.w + b4.w;
                As4[kk * 16 + rr] = p;
            }
        }
        __syncthreads();
    }

    // ---- straight-line compute: K=256, no further syncs ----------------
    int lr  = tid >> 4;                  // 0..15
    int lc2 = (tid & 15) * 2;            // 0,2,...,30
    float acc0 = 0.f, acc1 = 0.f;

#pragma unroll 16
    for (int kk4 = 0; kk4 < 64; kk4++) {
        float4 a4 = As4[kk4 * 16 + lr];
        const float* brow = &Bs[(kk4 * 4) * 32 + lc2];
        float2 b0 = *(const float2*)&brow[0 * 32];
        float2 b1 = *(const float2*)&brow[1 * 32];
        float2 b2 = *(const float2*)&brow[2 * 32];
        float2 b3 = *(const float2*)&brow[3 * 32];
        acc0 += a4.x * b0.x; acc1 += a4.x * b0.y;
        acc0 += a4.y * b1.x; acc1 += a4.y * b1.y;
        acc0 += a4.z * b2.x; acc1 += a4.z * b2.y;
        acc0 += a4.w * b3.x; acc1 += a4.w * b3.y;
    }

    float2 o = make_float2(acc0, acc1);
    *(float2*)&C[(m0 + lr) * CD + n0 + lc2] = o;
}

// ---------------------------------------------------------------------------
// K2: dot_qk[b,h,j] = sum_d pq[b,j,h,d]*pk[b,j,h,d].  One warp per (b,h,j).
// grid=256, block=256.
// ---------------------------------------------------------------------------
__global__ __launch_bounds__(256)
void ct_dotqk_kernel() {
    int idx  = blockIdx.x * 8 + (threadIdx.x >> 5);   // b*1024 + h*128 + j
    int lane = threadIdx.x & 31;
    int b = idx >> 10;
    int rem = idx & 1023;
    int h = rem >> 7;
    int j = rem & 127;
    float v = g_pq[(b * CL + j) * CD + h * CDK + lane] *
              g_pk[(b * CL + j) * CD + h * CDK + lane];
#pragma unroll
    for (int o = 16; o > 0; o >>= 1) v += __shfl_xor_sync(0xFFFFFFFFu, v, o);
    if (lane == 0) g_dotqk[idx] = v;
}

// ---------------------------------------------------------------------------
// K3: fused attention per (b,i).  Prologue computes the time-kernel tables
// (chi, lb) once in smem; then warp h owns head h: shuffle-only softmax,
// attn write, and V-reduction.  grid=256 (b*128+i), block=256.
// ---------------------------------------------------------------------------
__global__ __launch_bounds__(256)
void ct_attn_kernel(const float* __restrict__ t,
                    const float* __restrict__ omega,
                    const float* __restrict__ s,
                    float* __restrict__ attn_out) {
    int bid = blockIdx.x;
    int b = bid >> 7;
    int i = bid & 127;
    int tid = threadIdx.x;
    int h = tid >> 5;
    int lane = tid & 31;
    int j0 = lane * 4;

    __shared__ float sh_lb[128];        // omega * INV_TEMP * psi
    __shared__ float sh_chi[128];       // sum_r exp(-dt*s_r)
    __shared__ float sh_ws[8][128];

    if (tid < 128) {
        int j = tid;
        float s0 = s[0], s1 = s[1], s2 = s[2], s3 = s[3];
        float dt = fabsf(t[b * CL + i] - t[b * CL + j]);
        float c0 = __expf(-dt * s0), c1 = __expf(-dt * s1);
        float c2 = __expf(-dt * s2), c3 = __expf(-dt * s3);
        sh_chi[j] = (c0 + c1) + (c2 + c3);
        float psi = (c0 * c0 + c1 * c1) + (c2 * c2 + c3 * c3);
        sh_lb[j] = omega[(b * CL + i) * CL + j] * C_INV_TEMP * psi;
    }
    __syncthreads();

    float4 dq = *(const float4*)&g_dotqk[b * (CH * CL) + h * CL + j0];
    float4 lb = *(const float4*)&sh_lb[j0];
    float4 ch = *(const float4*)&sh_chi[j0];

    float l0 = (j0 + 0 <= i) ? lb.x * dq.x : -1e9f;
    float l1 = (j0 + 1 <= i) ? lb.y * dq.y : -1e9f;
    float l2 = (j0 + 2 <= i) ? lb.z * dq.z : -1e9f;
    float l3 = (j0 + 3 <= i) ? lb.w * dq.w : -1e9f;

    float m = fmaxf(fmaxf(l0, l1), fmaxf(l2, l3));
#pragma unroll
    for (int o = 16; o > 0; o >>= 1)
        m = fmaxf(m, __shfl_xor_sync(0xFFFFFFFFu, m, o));

    float e0 = __expf(l0 - m), e1 = __expf(l1 - m);
    float e2 = __expf(l2 - m), e3 = __expf(l3 - m);
    float su = (e0 + e1) + (e2 + e3);
#pragma unroll
    for (int o = 16; o > 0; o >>= 1)
        su += __shfl_xor_sync(0xFFFFFFFFu, su, o);

    float inv = 1.0f / su;
    float4 a4 = make_float4(e0 * inv, e1 * inv, e2 * inv, e3 * inv);
    *(float4*)&attn_out[((b * CH + h) * CL + i) * CL + j0] = a4;

    float4 w4 = make_float4(a4.x * ch.x, a4.y * ch.y, a4.z * ch.z, a4.w * ch.w);
    *(float4*)&sh_ws[h][j0] = w4;
    __syncwarp();

    // V reduction: outhead[b,i,h,d] = sum_j ws[h][j] * pv[b,j,h,d]
    const float* pvp = g_pv + b * CL * CD + h * CDK + lane;
    const float* wsp = sh_ws[h];
    float a0 = 0.f, a1 = 0.f, a2 = 0.f, a3 = 0.f;
#pragma unroll 8
    for (int j = 0; j < 128; j += 4) {
        a0 += wsp[j + 0] * pvp[(j + 0) * CD];
        a1 += wsp[j + 1] * pvp[(j + 1) * CD];
        a2 += wsp[j + 2] * pvp[(j + 2) * CD];
        a3 += wsp[j + 3] * pvp[(j + 3) * CD];
    }
    g_outhead[bid * CD + h * CDK + lane] = (a0 + a1) + (a2 + a3);
}

// ---------------------------------------------------------------------------
// K4: out = outhead @ fc_w + fc_b + q (residual).
// grid=(8,16) = 128 blocks, 256 threads; one-shot 48KB tile, no k-loop.
// ---------------------------------------------------------------------------
__global__ __launch_bounds__(256)
void ct_final_kernel(const float* __restrict__ W,
                     const float* __restrict__ bias,
                     const float* __restrict__ resid,
                     float* __restrict__ out) {
    __shared__ float4 As4[64 * 16];     // 16 KB
    __shared__ float  Bs[256 * 32];     // 32 KB

    int tid = threadIdx.x;
    int m0 = blockIdx.y * 16, n0 = blockIdx.x * 32;

    {
        int r   = tid & 15;
        int kk4 = tid >> 4;
#pragma unroll
        for (int it = 0; it < 4; it++) {
            int kk = kk4 + it * 16;
            __pipeline_memcpy_async(&As4[kk * 16 + r],
                                    &g_outhead[(m0 + r) * CD + kk * 4], 16);
        }
    }
    {
        int c4 = tid & 7;
        int k0 = tid >> 3;
#pragma unroll
        for (int it = 0; it < 8; it++) {
            int k = k0 + it * 32;
            __pipeline_memcpy_async(&Bs[k * 32 + c4 * 4],
                                    &W[k * CD + n0 + c4 * 4], 16);
        }
    }
    __pipeline_commit();
    __pipeline_wait_prior(0);
    __syncthreads();

    int lr  = tid >> 4;
    int lc2 = (tid & 15) * 2;
    float acc0 = 0.f, acc1 = 0.f;

#pragma unroll 16
    for (int kk4 = 0; kk4 < 64; kk4++) {
        float4 a4 = As4[kk4 * 16 + lr];
        const float* brow = &Bs[(kk4 * 4) * 32 + lc2];
        float2 b0 = *(const float2*)&brow[0 * 32];
        float2 b1 = *(const float2*)&brow[1 * 32];
        float2 b2 = *(const float2*)&brow[2 * 32];
        float2 b3 = *(const float2*)&brow[3 * 32];
        acc0 += a4.x * b0.x; acc1 += a4.x * b0.y;
        acc0 += a4.y * b1.x; acc1 += a4.y * b1.y;
        acc0 += a4.z * b2.x; acc1 += a4.z * b2.y;
        acc0 += a4.w * b3.x; acc1 += a4.w * b3.y;
    }

    int row = m0 + lr, col = n0 + lc2;
    float2 bi = *(const float2*)&bias[col];
    float2 re = *(const float2*)&resid[row * CD + col];
    float2 o  = make_float2(acc0 + bi.x + re.x, acc1 + bi.y + re.y);
    *(float2*)&out[row * CD + col] = o;
}

// ---------------------------------------------------------------------------
// Launch.  Inputs: q,k,v,t,omega,mask,Wq,Wk,Wv,s,fc_w,fc_b,ln_g,ln_b
// Output: out (65536 f32) then attn (262144 f32)
// ---------------------------------------------------------------------------
extern "C" void kernel_launch(void* const* d_in, const int* in_sizes, int n_in,
                              void* d_out, int out_size) {
    const float* q     = (const float*)d_in[0];
    const float* k     = (const float*)d_in[1];
    const float* v     = (const float*)d_in[2];
    const float* t     = (const float*)d_in[3];
    const float* omega = (const float*)d_in[4];
    // d_in[5] = mask (causal triu) -- applied analytically
    const float* Wq    = (const float*)d_in[6];
    const float* Wk    = (const float*)d_in[7];
    const float* Wv    = (const float*)d_in[8];
    const float* s     = (const float*)d_in[9];
    const float* fc_w  = (const float*)d_in[10];
    const float* fc_b  = (const float*)d_in[11];
    const float* ln_g  = (const float*)d_in[12];
    const float* ln_b  = (const float*)d_in[13];

    float* out      = (float*)d_out;
    float* attn_out = out + CB * CL * CD;

    ct_gemm3_kernel<<<dim3(8, 16, 3), 256>>>(q, k, v, Wq, Wk, Wv, ln_g, ln_b);
    ct_dotqk_kernel<<<256, 256>>>();
    ct_attn_kernel<<<CB * CL, 256>>>(t, omega, s, attn_out);
    ct_final_kernel<<<dim3(8, 16), 256>>>(fc_w, fc_b, q, out);
}

// round 12
// speedup vs baseline: 1.0850x; 1.0850x over previous
#include <cuda_runtime.h>
#include <cuda_bf16.h>
#include <cuda_pipeline.h>

// Problem constants (constexpr, not macros)
constexpr int CB  = 2;     // batch
constexpr int CL  = 128;   // seq len
constexpr int CD  = 256;   // model dim
constexpr int CH  = 8;     // heads
constexpr int CDK = 32;    // head dim
constexpr float C_EPS = 1e-6f;
constexpr float C_INV_TEMP = 0.17677669529663687f;   // 1/sqrt(32)

// Scratch (allocation-free rule: __device__ globals)
__device__ float g_pv[CB * CL * CD];
__device__ float g_dotqk[CB * CH * CL];
__device__ float g_outhead[CB * CL * CD];

extern __shared__ float sm_dyn[];

// ---------------------------------------------------------------------------
// K1: projection kernel.  grid=(8,16,2), block=256, dynamic smem 96KB.
//  z=0: fused Q&K projection for head bx, rows [m0,m0+16): computes
//       pq,pk tiles in registers and writes ONLY dot_qk[b,h,j] (pq/pk
//       never touch global memory).  LN fused on the q operand.
//  z=1: V projection tile -> g_pv.
// Layout (floats): A1 f4[1024] @0 (16KB) | A2 f4[1024] @16KB |
//                  B1[8192] @32KB (32KB) | B2[8192] @64KB
// ---------------------------------------------------------------------------
__global__ __launch_bounds__(256)
void ct_proj_kernel(const float* __restrict__ qin,
                    const float* __restrict__ kin,
                    const float* __restrict__ vin,
                    const float* __restrict__ Wq,
                    const float* __restrict__ Wk,
                    const float* __restrict__ Wv,
                    const float* __restrict__ ln_g,
                    const float* __restrict__ ln_b) {
    const int bz = blockIdx.z;
    int tid = threadIdx.x;
    int n0 = blockIdx.x * 32, m0 = blockIdx.y * 16;

    float4* A1 = (float4*)sm_dyn;            // q (or v) tile, float4-interleaved
    float4* A2 = (float4*)(sm_dyn + 4096);   // k tile (z=0 only)
    float*  B1 = sm_dyn + 8192;              // Wq (or Wv) tile
    float*  B2 = sm_dyn + 16384;             // Wk tile (z=0 only)

    int lr  = tid >> 4;                      // 0..15 (output row)
    int lc2 = (tid & 15) * 2;                // output col pair

    if (bz == 0) {
        // ---- issue all async copies (q,k,Wq,Wk) ------------------------
        {
            int r = tid & 15, kk4 = tid >> 4;
#pragma unroll
            for (int it = 0; it < 4; it++) {
                int kk = kk4 + it * 16;
                __pipeline_memcpy_async(&A1[kk * 16 + r], &qin[(m0 + r) * CD + kk * 4], 16);
                __pipeline_memcpy_async(&A2[kk * 16 + r], &kin[(m0 + r) * CD + kk * 4], 16);
            }
            int c4 = tid & 7, k0 = tid >> 3;
#pragma unroll
            for (int it = 0; it < 8; it++) {
                int kx = k0 + it * 32;
                __pipeline_memcpy_async(&B1[kx * 32 + c4 * 4], &Wq[kx * CD + n0 + c4 * 4], 16);
                __pipeline_memcpy_async(&B2[kx * 32 + c4 * 4], &Wk[kx * CD + n0 + c4 * 4], 16);
            }
        }
        __pipeline_commit();

        // ---- LN stats from global while copies fly (warp w: rows w,w+8)
        int w = tid >> 5, lane = tid & 31;
        float mu_a, rs_a, mu_b, rs_b;
#pragma unroll
        for (int half = 0; half < 2; half++) {
            int rr = w + half * 8;
            const float* rowp = qin + (m0 + rr) * CD;
            float s1 = 0.f, s2 = 0.f;
#pragma unroll
            for (int e = 0; e < 8; e++) {
                float x = rowp[lane + 32 * e];
                s1 += x; s2 += x * x;
            }
#pragma unroll
            for (int o = 16; o > 0; o >>= 1) {
                s1 += __shfl_xor_sync(0xFFFFFFFFu, s1, o);
                s2 += __shfl_xor_sync(0xFFFFFFFFu, s2, o);
            }
            float mu  = s1 * (1.0f / 256.0f);
            float var = s2 * (1.0f / 256.0f) - mu * mu;
            float rs  = rsqrtf(var + C_EPS);
            if (half == 0) { mu_a = mu; rs_a = rs; }
            else           { mu_b = mu; rs_b = rs; }
        }

        __pipeline_wait_prior(0);
        __syncthreads();

        // ---- in-smem LN transform of A1 (warp w owns rows w, w+8) ------
#pragma unroll
        for (int half = 0; half < 2; half++) {
            int rr = half ? (w + 8) : w;
            float mu = half ? mu_b : mu_a;
            float rs = half ? rs_b : rs_a;
#pragma unroll
            for (int c = 0; c < 2; c++) {
                int kk = lane + c * 32;
                float4 p  = A1[kk * 16 + rr];
                float4 g4 = ((const float4*)ln_g)[kk];
                float4 b4 = ((const float4*)ln_b)[kk];
                p.x = (p.x - mu) * rs * g4.x + b4.x;
                p.y = (p.y - mu) * rs * g4.y + b4.y;
                p.z = (p.z - mu) * rs * g4.z + b4.z;
                p.w = (p.w - mu) * rs * g4.w + b4.w;
                A1[kk * 16 + rr] = p;
            }
        }
        __syncthreads();

        // ---- compute pq,pk tiles in registers --------------------------
        float aq0 = 0.f, aq1 = 0.f, ak0 = 0.f, ak1 = 0.f;
#pragma unroll 8
        for (int kk4 = 0; kk4 < 64; kk4++) {
            float4 a_q = A1[kk4 * 16 + lr];
            float4 a_k = A2[kk4 * 16 + lr];
            const float* bq = &B1[(kk4 * 4) * 32 + lc2];
            const float* bk = &B2[(kk4 * 4) * 32 + lc2];
            float2 q0 = *(const float2*)&bq[0 * 32];
            float2 q1 = *(const float2*)&bq[1 * 32];
            float2 q2 = *(const float2*)&bq[2 * 32];
            float2 q3 = *(const float2*)&bq[3 * 32];
            aq0 += a_q.x * q0.x; aq1 += a_q.x * q0.y;
            aq0 += a_q.y * q1.x; aq1 += a_q.y * q1.y;
            aq0 += a_q.z * q2.x; aq1 += a_q.z * q2.y;
            aq0 += a_q.w * q3.x; aq1 += a_q.w * q3.y;
            float2 k0v = *(const float2*)&bk[0 * 32];
            float2 k1v = *(const float2*)&bk[1 * 32];
            float2 k2v = *(const float2*)&bk[2 * 32];
            float2 k3v = *(const float2*)&bk[3 * 32];
            ak0 += a_k.x * k0v.x; ak1 += a_k.x * k0v.y;
            ak0 += a_k.y * k1v.x; ak1 += a_k.y * k1v.y;
            ak0 += a_k.z * k2v.x; ak1 += a_k.z * k2v.y;
            ak0 += a_k.w * k3v.x; ak1 += a_k.w * k3v.y;
        }

        // ---- dot over the head dim (cols n0..n0+31 = full head bx) -----
        float part = aq0 * ak0 + aq1 * ak1;
#pragma unroll
        for (int o = 1; o < 16; o <<= 1)
            part += __shfl_xor_sync(0xFFFFFFFFu, part, o);
        if ((tid & 15) == 0) {
            int m = m0 + lr;                 // global row = b*128 + j
            g_dotqk[(m >> 7) * (CH * CL) + blockIdx.x * CL + (m & 127)] = part;
        }
    } else {
        // ---- V projection ----------------------------------------------
        {
            int r = tid & 15, kk4 = tid >> 4;
#pragma unroll
            for (int it = 0; it < 4; it++) {
                int kk = kk4 + it * 16;
                __pipeline_memcpy_async(&A1[kk * 16 + r], &vin[(m0 + r) * CD + kk * 4], 16);
            }
            int c4 = tid & 7, k0 = tid >> 3;
#pragma unroll
            for (int it = 0; it < 8; it++) {
                int kx = k0 + it * 32;
                __pipeline_memcpy_async(&B1[kx * 32 + c4 * 4], &Wv[kx * CD + n0 + c4 * 4], 16);
            }
        }
        __pipeline_commit();
        __pipeline_wait_prior(0);
        __syncthreads();

        float acc0 = 0.f, acc1 = 0.f;
#pragma unroll 16
        for (int kk4 = 0; kk4 < 64; kk4++) {
            float4 a4 = A1[kk4 * 16 + lr];
            const float* brow = &B1[(kk4 * 4) * 32 + lc2];
            float2 b0 = *(const float2*)&brow[0 * 32];
            float2 b1 = *(const float2*)&brow[1 * 32];
            float2 b2 = *(const float2*)&brow[2 * 32];
            float2 b3 = *(const float2*)&brow[3 * 32];
            acc0 += a4.x * b0.x; acc1 += a4.x * b0.y;
            acc0 += a4.y * b1.x; acc1 += a4.y * b1.y;
            acc0 += a4.z * b2.x; acc1 += a4.z * b2.y;
            acc0 += a4.w * b3.x; acc1 += a4.w * b3.y;
        }
        *(float2*)&g_pv[(m0 + lr) * CD + n0 + lc2] = make_float2(acc0, acc1);
    }
}

// ---------------------------------------------------------------------------
// K2: fused attention per (b,i).  Prologue computes time-kernel tables
// (chi, lb) in smem; warp h owns head h: shuffle-only softmax, attn write,
// V-reduction.  grid=256 (b*128+i), block=256, static smem.
// ---------------------------------------------------------------------------
__global__ __launch_bounds__(256)
void ct_attn_kernel(const float* __restrict__ t,
                    const float* __restrict__ omega,
                    const float* __restrict__ s,
                    float* __restrict__ attn_out) {
    int bid = blockIdx.x;
    int b = bid >> 7;
    int i = bid & 127;
    int tid = threadIdx.x;
    int h = tid >> 5;
    int lane = tid & 31;
    int j0 = lane * 4;

    __shared__ float sh_lb[128];        // omega * INV_TEMP * psi
    __shared__ float sh_chi[128];       // sum_r exp(-dt*s_r)
    __shared__ float sh_ws[8][128];

    if (tid < 128) {
        int j = tid;
        float s0 = s[0], s1 = s[1], s2 = s[2], s3 = s[3];
        float dt = fabsf(t[b * CL + i] - t[b * CL + j]);
        float c0 = __expf(-dt * s0), c1 = __expf(-dt * s1);
        float c2 = __expf(-dt * s2), c3 = __expf(-dt * s3);
        sh_chi[j] = (c0 + c1) + (c2 + c3);
        float psi = (c0 * c0 + c1 * c1) + (c2 * c2 + c3 * c3);
        sh_lb[j] = omega[(b * CL + i) * CL + j] * C_INV_TEMP * psi;
    }
    __syncthreads();

    float4 dq = *(const float4*)&g_dotqk[b * (CH * CL) + h * CL + j0];
    float4 lb = *(const float4*)&sh_lb[j0];
    float4 ch = *(const float4*)&sh_chi[j0];

    float l0 = (j0 + 0 <= i) ? lb.x * dq.x : -1e9f;
    float l1 = (j0 + 1 <= i) ? lb.y * dq.y : -1e9f;
    float l2 = (j0 + 2 <= i) ? lb.z * dq.z : -1e9f;
    float l3 = (j0 + 3 <= i) ? lb.w * dq.w : -1e9f;

    float m = fmaxf(fmaxf(l0, l1), fmaxf(l2, l3));
#pragma unroll
    for (int o = 16; o > 0; o >>= 1)
        m = fmaxf(m, __shfl_xor_sync(0xFFFFFFFFu, m, o));

    float e0 = __expf(l0 - m), e1 = __expf(l1 - m);
    float e2 = __expf(l2 - m), e3 = __expf(l3 - m);
    float su = (e0 + e1) + (e2 + e3);
#pragma unroll
    for (int o = 16; o > 0; o >>= 1)
        su += __shfl_xor_sync(0xFFFFFFFFu, su, o);

    float inv = 1.0f / su;
    float4 a4 = make_float4(e0 * inv, e1 * inv, e2 * inv, e3 * inv);
    *(float4*)&attn_out[((b * CH + h) * CL + i) * CL + j0] = a4;

    float4 w4 = make_float4(a4.x * ch.x, a4.y * ch.y, a4.z * ch.z, a4.w * ch.w);
    *(float4*)&sh_ws[h][j0] = w4;
    __syncwarp();

    // V reduction: outhead[b,i,h,d] = sum_j ws[h][j] * pv[b,j,h,d]
    const float* pvp = g_pv + b * CL * CD + h * CDK + lane;
    const float* wsp = sh_ws[h];
    float a0 = 0.f, a1 = 0.f, a2 = 0.f, a3 = 0.f;
#pragma unroll 8
    for (int j = 0; j < 128; j += 4) {
        a0 += wsp[j + 0] * pvp[(j + 0) * CD];
        a1 += wsp[j + 1] * pvp[(j + 1) * CD];
        a2 += wsp[j + 2] * pvp[(j + 2) * CD];
        a3 += wsp[j + 3] * pvp[(j + 3) * CD];
    }
    g_outhead[bid * CD + h * CDK + lane] = (a0 + a1) + (a2 + a3);
}

// ---------------------------------------------------------------------------
// K3: out = outhead @ fc_w + fc_b + q (residual).
// grid=(8,16), block=512: split-K x2 (each half does K=128), smem combine.
// Dynamic smem 50KB: A4 f4[1024] @0 | Bs[8192] @16KB | red[512] @48KB.
// ---------------------------------------------------------------------------
__global__ __launch_bounds__(512)
void ct_final_kernel(const float* __restrict__ W,
                     const float* __restrict__ bias,
                     const float* __restrict__ resid,
                     float* __restrict__ out) {
    float4* A4  = (float4*)sm_dyn;
    float*  Bs  = sm_dyn + 4096;
    float*  red = sm_dyn + 4096 + 8192;

    int tid = threadIdx.x;
    int m0 = blockIdx.y * 16, n0 = blockIdx.x * 32;

    {
        int r = tid & 15, kk4g = tid >> 4;       // 0..31
#pragma unroll
        for (int it = 0; it < 2; it++) {
            int kk = kk4g + it * 32;
            __pipeline_memcpy_async(&A4[kk * 16 + r],
                                    &g_outhead[(m0 + r) * CD + kk * 4], 16);
        }
        int c4 = tid & 7, k0 = tid >> 3;         // 0..63
#pragma unroll
        for (int it = 0; it < 4; it++) {
            int kx = k0 + it * 64;
            __pipeline_memcpy_async(&Bs[kx * 32 + c4 * 4],
                                    &W[kx * CD + n0 + c4 * 4], 16);
        }
    }
    __pipeline_commit();
    __pipeline_wait_prior(0);
    __syncthreads();

    int g   = tid >> 8;                  // split-K half
    int idx = tid & 255;
    int lr  = idx >> 4;
    int lc2 = (idx & 15) * 2;
    float acc0 = 0.f, acc1 = 0.f;
    int base = g * 32;

#pragma unroll 16
    for (int kk = 0; kk < 32; kk++) {
        int kk4 = base + kk;
        float4 a4 = A4[kk4 * 16 + lr];
        const float* brow = &Bs[(kk4 * 4) * 32 + lc2];
        float2 b0 = *(const float2*)&brow[0 * 32];
        float2 b1 = *(const float2*)&brow[1 * 32];
        float2 b2 = *(const float2*)&brow[2 * 32];
        float2 b3 = *(const float2*)&brow[3 * 32];
        acc0 += a4.x * b0.x; acc1 += a4.x * b0.y;
        acc0 += a4.y * b1.x; acc1 += a4.y * b1.y;
        acc0 += a4.z * b2.x; acc1 += a4.z * b2.y;
        acc0 += a4.w * b3.x; acc1 += a4.w * b3.y;
    }

    if (g == 1) {
        red[idx * 2 + 0] = acc0;
        red[idx * 2 + 1] = acc1;
    }
    __syncthreads();
    if (g == 0) {
        acc0 += red[idx * 2 + 0];
        acc1 += red[idx * 2 + 1];
        int row = m0 + lr, col = n0 + lc2;
        float2 bi = *(const float2*)&bias[col];
        float2 re = *(const float2*)&resid[row * CD + col];
        *(float2*)&out[row * CD + col] =
            make_float2(acc0 + bi.x + re.x, acc1 + bi.y + re.y);
    }
}

// ---------------------------------------------------------------------------
// Launch.  Inputs: q,k,v,t,omega,mask,Wq,Wk,Wv,s,fc_w,fc_b,ln_g,ln_b
// Output: out (65536 f32) then attn (262144 f32)
// ---------------------------------------------------------------------------
extern "C" void kernel_launch(void* const* d_in, const int* in_sizes, int n_in,
                              void* d_out, int out_size) {
    const float* q     = (const float*)d_in[0];
    const float* k     = (const float*)d_in[1];
    const float* v     = (const float*)d_in[2];
    const float* t     = (const float*)d_in[3];
    const float* omega = (const float*)d_in[4];
    // d_in[5] = mask (causal triu) -- applied analytically
    const float* Wq    = (const float*)d_in[6];
    const float* Wk    = (const float*)d_in[7];
    const float* Wv    = (const float*)d_in[8];
    const float* s     = (const float*)d_in[9];
    const float* fc_w  = (const float*)d_in[10];
    const float* fc_b  = (const float*)d_in[11];
    const float* ln_g  = (const float*)d_in[12];
    const float* ln_b  = (const float*)d_in[13];

    float* out      = (float*)d_out;
    float* attn_out = out + CB * CL * CD;

    // Opt in to >48KB dynamic smem (capture-time host calls; not stream ops)
    cudaFuncSetAttribute(ct_proj_kernel,
                         cudaFuncAttributeMaxDynamicSharedMemorySize, 96 * 1024);
    cudaFuncSetAttribute(ct_final_kernel,
                         cudaFuncAttributeMaxDynamicSharedMemorySize, 50 * 1024);

    ct_proj_kernel<<<dim3(8, 16, 2), 256, 96 * 1024>>>(q, k, v, Wq, Wk, Wv, ln_g, ln_b);
    ct_attn_kernel<<<CB * CL, 256>>>(t, omega, s, attn_out);
    ct_final_kernel<<<dim3(8, 16), 512, 50 * 1024>>>(fc_w, fc_b, q, out);
}